// round 8
// baseline (speedup 1.0000x reference)
#include <cuda_runtime.h>
#include <cuda_bf16.h>
#include <cstdint>

#define BB 16
#define CC 64
#define HH 192
#define WWID 192
#define HWSZ (HH * WWID)          // 36864
#define NSTEPS (BB * 128 * 512)   // 1,048,576 path steps
#define TPX 128                   // pixels per block tile (MMA M)

__device__ unsigned char g_occ[BB * HWSZ];
__device__ int g_idx_is64;

// ---------------------------------------------------------------------------
// Zero occupancy flags + probe path_idx element width (int64 hi-words == 0).
// ---------------------------------------------------------------------------
__global__ void zero_probe_kernel(const int* __restrict__ words) {
    int i = blockIdx.x * blockDim.x + threadIdx.x;
    uint4* p = reinterpret_cast<uint4*>(g_occ);
    if (i < (BB * HWSZ) / 16) p[i] = make_uint4(0u, 0u, 0u, 0u);
    if (i == 0) g_idx_is64 = 1;
    __threadfence();
    if (i < 1024 && words[2 * i + 1] != 0) atomicAnd(&g_idx_is64, 0);
}

__global__ void mark_occ_kernel(const void* __restrict__ path_idx) {
    int i = blockIdx.x * blockDim.x + threadIdx.x;
    if (i < NSTEPS) {
        int b = i >> 16;
        int hw;
        if (g_idx_is64)
            hw = (int)((const long long*)path_idx)[i];
        else
            hw = ((const int*)path_idx)[i];
        if ((unsigned)hw < (unsigned)HWSZ)
            g_occ[b * HWSZ + hw] = 1;
    }
}

// ---------------------------------------------------------------------------
__device__ __forceinline__ uint32_t smem_u32(const void* p) {
    uint32_t a;
    asm("{ .reg .u64 t; cvta.to.shared.u64 t, %1; cvt.u32.u64 %0, t; }"
        : "=r"(a) : "l"(p));
    return a;
}
// SW128-style swizzle on 128B rows of 16B chunks
#define SWZ(o) ((uint32_t)(o) ^ ((((uint32_t)(o)) >> 3) & 0x70))

#define LDSM4(R, ADDR)                                                        \
    asm volatile("ldmatrix.sync.aligned.m8n8.x4.shared.b16 {%0,%1,%2,%3}, [%4];" \
                 : "=r"((R)[0]), "=r"((R)[1]), "=r"((R)[2]), "=r"((R)[3])     \
                 : "r"(ADDR))

#define MMA16816(C, A, B0, B1)                                                \
    asm volatile("mma.sync.aligned.m16n8k16.row.col.f32.bf16.bf16.f32 "       \
                 "{%0,%1,%2,%3}, {%4,%5,%6,%7}, {%8,%9}, {%0,%1,%2,%3};"      \
                 : "+f"((C)[0]), "+f"((C)[1]), "+f"((C)[2]), "+f"((C)[3])     \
                 : "r"((A)[0]), "r"((A)[1]), "r"((A)[2]), "r"((A)[3]),        \
                   "r"(B0), "r"(B1))

#define CP_ASYNC16(DST, SRC)                                                  \
    asm volatile("cp.async.cg.shared.global [%0], [%1], 16;"                  \
                 :: "r"(DST), "l"(SRC) : "memory")

// ---------------------------------------------------------------------------
// Masked GEMM via mma.sync bf16 3-way split (hi*hi + hi*lo + lo*hi, f32 acc).
// Staging: cp.async gmem->smem f32 (4 k-stages of 16 rows), convert from smem.
// Register footprint of staging ~0 -> 4 CTAs/SM without spills.
// ---------------------------------------------------------------------------
__global__ void __launch_bounds__(128, 4)
mma_gemm_kernel(const float* __restrict__ feat,
                const float* __restrict__ Wm,     // [64][64] (k, c)
                const float* __restrict__ bm,     // [64]
                float* __restrict__ out) {
    __shared__ __align__(1024) unsigned char sAhi[TPX * 128];  // 16 KB
    __shared__ __align__(1024) unsigned char sAlo[TPX * 128];  // 16 KB
    __shared__ __align__(1024) unsigned char sBhi[64 * 128];   // 8 KB
    __shared__ __align__(1024) unsigned char sBlo[64 * 128];   // 8 KB
    __shared__ __align__(1024) float sF[16 * 128];             // 8 KB (56 KB tot)

    const int tid  = threadIdx.x;
    const int warp = tid >> 5;
    const int lane = tid & 31;
    const int b    = blockIdx.y;
    const int hw0  = blockIdx.x * TPX;

    // --- Stage B = W^T split. Bt[n][k] = Wm[k][n]; rows of 64 bf16 = 128 B ---
    for (int i = tid; i < 64 * 64; i += 128) {
        int n = i & 63;           // lanes -> consecutive n (coalesced gmem read)
        int k = i >> 6;
        float w = Wm[k * 64 + n];
        __nv_bfloat16 h = __float2bfloat16(w);
        __nv_bfloat16 l = __float2bfloat16(w - __bfloat162float(h));
        uint32_t off = SWZ((uint32_t)(n * 128 + k * 2));
        *reinterpret_cast<unsigned short*>(sBhi + off) = __bfloat16_as_ushort(h);
        *reinterpret_cast<unsigned short*>(sBlo + off) = __bfloat16_as_ushort(l);
    }

    // --- Stage A in 4 k-stages: cp.async f32 tile slab, convert to bf16 split ---
    {
        const uint32_t sFaddr = smem_u32(sF);
        const uint32_t aHi = smem_u32(sAhi);
        const uint32_t aLo = smem_u32(sAlo);
        const float* gsrc0 = feat + (size_t)b * CC * HWSZ + hw0;

        for (int s = 0; s < 4; s++) {
            // 16 rows x 128 px x 4B = 512 float4; 4 per thread, coalesced
            const float* gs = gsrc0 + (size_t)(s * 16) * HWSZ;
            #pragma unroll
            for (int j = 0; j < 4; j++) {
                int idx = tid + j * 128;          // 0..511
                int row = idx >> 5;               // 0..15
                int col = (idx & 31) << 4;        // byte offset within 512B row
                CP_ASYNC16(sFaddr + row * 512 + col,
                           (const char*)(gs + (size_t)row * HWSZ) + col);
            }
            asm volatile("cp.async.commit_group;" ::: "memory");
            asm volatile("cp.async.wait_group 0;" ::: "memory");
            __syncthreads();

            // Convert: thread = pixel; 16 conflict-free LDS.32, pack, 4 STS.128
            float v[16];
            #pragma unroll
            for (int j = 0; j < 16; j++) v[j] = sF[j * 128 + tid];
            uint32_t hp[8], lp[8];
            #pragma unroll
            for (int j = 0; j < 8; j++) {
                __nv_bfloat16 h0 = __float2bfloat16(v[2 * j]);
                __nv_bfloat16 h1 = __float2bfloat16(v[2 * j + 1]);
                __nv_bfloat16 l0 = __float2bfloat16(v[2 * j] - __bfloat162float(h0));
                __nv_bfloat16 l1 = __float2bfloat16(v[2 * j + 1] - __bfloat162float(h1));
                hp[j] = (uint32_t)__bfloat16_as_ushort(h0) |
                        ((uint32_t)__bfloat16_as_ushort(h1) << 16);
                lp[j] = (uint32_t)__bfloat16_as_ushort(l0) |
                        ((uint32_t)__bfloat16_as_ushort(l1) << 16);
            }
            const uint32_t base = (uint32_t)tid * 128 + (uint32_t)s * 32;
            const uint32_t o0 = SWZ(base), o1 = SWZ(base + 16);
            asm volatile("st.shared.v4.b32 [%0], {%1, %2, %3, %4};"
                         :: "r"(aHi + o0), "r"(hp[0]), "r"(hp[1]), "r"(hp[2]), "r"(hp[3]) : "memory");
            asm volatile("st.shared.v4.b32 [%0], {%1, %2, %3, %4};"
                         :: "r"(aHi + o1), "r"(hp[4]), "r"(hp[5]), "r"(hp[6]), "r"(hp[7]) : "memory");
            asm volatile("st.shared.v4.b32 [%0], {%1, %2, %3, %4};"
                         :: "r"(aLo + o0), "r"(lp[0]), "r"(lp[1]), "r"(lp[2]), "r"(lp[3]) : "memory");
            asm volatile("st.shared.v4.b32 [%0], {%1, %2, %3, %4};"
                         :: "r"(aLo + o1), "r"(lp[4]), "r"(lp[5]), "r"(lp[6]), "r"(lp[7]) : "memory");
            __syncthreads();   // protect sF before next stage overwrites
        }
    }

    // --- Fragment addressing (XOR applied to composed chunk offset) ---
    const int g = lane >> 2, t = lane & 3;
    const int px = warp * 32;
    const uint32_t mask   = (uint32_t)(lane & 7) << 4;
    const uint32_t aRow   = (uint32_t)(px + (lane & 15)) * 128;
    const uint32_t aChunk = (uint32_t)(lane & 16);
    const uint32_t bRow   = (uint32_t)((lane & 7) + ((lane & 16) >> 1)) * 128;
    const uint32_t bChunk = (uint32_t)((lane & 8) << 1);

    // Prefetch epilogue operands (overlap with MMA latency)
    const unsigned char* occp = g_occ + b * HWSZ + hw0 + px + g;
    unsigned char oc0 = occp[0], oc1 = occp[8], oc2 = occp[16], oc3 = occp[24];
    float bias0[8], bias1[8];
    #pragma unroll
    for (int n = 0; n < 8; n++) {
        bias0[n] = __ldg(&bm[n * 8 + 2 * t]);
        bias1[n] = __ldg(&bm[n * 8 + 2 * t + 1]);
    }

    float c_[2][8][4];
    #pragma unroll
    for (int m = 0; m < 2; m++)
        #pragma unroll
        for (int n = 0; n < 8; n++)
            #pragma unroll
            for (int r = 0; r < 4; r++) c_[m][n][r] = 0.0f;

    const uint32_t aBases[3] = { smem_u32(sAhi), smem_u32(sAhi), smem_u32(sAlo) };
    const uint32_t bBases[3] = { smem_u32(sBhi), smem_u32(sBlo), smem_u32(sBhi) };

    #pragma unroll
    for (int ps = 0; ps < 3; ps++) {
        const uint32_t aB = aBases[ps] + aRow;
        const uint32_t bB = bBases[ps] + bRow;
        #pragma unroll
        for (int k = 0; k < 4; k++) {
            const uint32_t ac = (aChunk + (uint32_t)k * 32) ^ mask;  // <=112, no carry
            const uint32_t bc = (bChunk + (uint32_t)k * 32) ^ mask;
            uint32_t a0[4], a1[4];
            LDSM4(a0, aB + ac);
            LDSM4(a1, aB + 2048 + ac);
            uint32_t bf[8][2];
            #pragma unroll
            for (int np = 0; np < 4; np++) {
                uint32_t r4[4];
                LDSM4(r4, bB + (uint32_t)np * 2048 + bc);
                bf[2 * np][0] = r4[0]; bf[2 * np][1] = r4[1];
                bf[2 * np + 1][0] = r4[2]; bf[2 * np + 1][1] = r4[3];
            }
            #pragma unroll
            for (int n = 0; n < 8; n++) {
                MMA16816(c_[0][n], a0, bf[n][0], bf[n][1]);
                MMA16816(c_[1][n], a1, bf[n][0], bf[n][1]);
            }
        }
    }

    // --- Epilogue: mask + bias; per-channel stores are full 32B sectors ---
    float msk[4];
    msk[0] = oc0 ? 1.0f : 0.0f;
    msk[1] = oc1 ? 1.0f : 0.0f;
    msk[2] = oc2 ? 1.0f : 0.0f;
    msk[3] = oc3 ? 1.0f : 0.0f;

    float* ob = out + (size_t)b * CC * HWSZ;
    #pragma unroll
    for (int m = 0; m < 2; m++) {
        const int hwA = hw0 + px + m * 16 + g;
        const int hwB = hwA + 8;
        const float mA = msk[2 * m], mB = msk[2 * m + 1];
        #pragma unroll
        for (int n = 0; n < 8; n++) {
            const size_t ch = (size_t)(n * 8 + 2 * t);
            ob[ch * HWSZ + hwA]       = (c_[m][n][0] + bias0[n]) * mA;
            ob[(ch + 1) * HWSZ + hwA] = (c_[m][n][1] + bias1[n]) * mA;
            ob[ch * HWSZ + hwB]       = (c_[m][n][2] + bias0[n]) * mB;
            ob[(ch + 1) * HWSZ + hwB] = (c_[m][n][3] + bias1[n]) * mB;
        }
    }
}

// ---------------------------------------------------------------------------
extern "C" void kernel_launch(void* const* d_in, const int* in_sizes, int n_in,
                              void* d_out, int out_size) {
    const float* feat = (const float*)d_in[0];      // [B, C, H, W] f32
    const void*  pidx = d_in[1];                    // [B, P, L] int32 or int64
    const float* Wm   = (const float*)d_in[2];      // [C, C] f32
    const float* bm   = (const float*)d_in[3];      // [C] f32
    float*       out  = (float*)d_out;              // [B, C, H, W] f32

    (void)in_sizes; (void)n_in; (void)out_size;

    zero_probe_kernel<<<(BB * HWSZ / 16 + 255) / 256, 256>>>((const int*)pidx);
    mark_occ_kernel<<<(NSTEPS + 255) / 256, 256>>>(pidx);

    dim3 grid(HWSZ / TPX, BB);   // 288 x 16 = 4608 tiles
    mma_gemm_kernel<<<grid, 128>>>(feat, Wm, bm, out);
}

// round 9
// speedup vs baseline: 1.0230x; 1.0230x over previous
#include <cuda_runtime.h>
#include <cuda_bf16.h>
#include <cstdint>

#define BB 16
#define CC 64
#define HH 192
#define WWID 192
#define HWSZ (HH * WWID)          // 36864
#define NSTEPS (BB * 128 * 512)   // 1,048,576 path steps
#define TPX 128                   // pixels per block tile (MMA M)

__device__ unsigned char g_occ[BB * HWSZ];
__device__ int g_idx_is64;

// ---------------------------------------------------------------------------
// Zero occupancy flags + probe path_idx element width (int64 hi-words == 0).
// ---------------------------------------------------------------------------
__global__ void zero_probe_kernel(const int* __restrict__ words) {
    int i = blockIdx.x * blockDim.x + threadIdx.x;
    uint4* p = reinterpret_cast<uint4*>(g_occ);
    if (i < (BB * HWSZ) / 16) p[i] = make_uint4(0u, 0u, 0u, 0u);
    if (i == 0) g_idx_is64 = 1;
    __threadfence();
    if (i < 1024 && words[2 * i + 1] != 0) atomicAnd(&g_idx_is64, 0);
}

__global__ void mark_occ_kernel(const void* __restrict__ path_idx) {
    int i = blockIdx.x * blockDim.x + threadIdx.x;
    if (i < NSTEPS) {
        int b = i >> 16;
        int hw;
        if (g_idx_is64)
            hw = (int)((const long long*)path_idx)[i];
        else
            hw = ((const int*)path_idx)[i];
        if ((unsigned)hw < (unsigned)HWSZ)
            g_occ[b * HWSZ + hw] = 1;
    }
}

// ---------------------------------------------------------------------------
__device__ __forceinline__ uint32_t smem_u32(const void* p) {
    uint32_t a;
    asm("{ .reg .u64 t; cvta.to.shared.u64 t, %1; cvt.u32.u64 %0, t; }"
        : "=r"(a) : "l"(p));
    return a;
}
#define SWZ(o) ((uint32_t)(o) ^ ((((uint32_t)(o)) >> 3) & 0x70))

#define LDSM4(R, ADDR)                                                        \
    asm volatile("ldmatrix.sync.aligned.m8n8.x4.shared.b16 {%0,%1,%2,%3}, [%4];" \
                 : "=r"((R)[0]), "=r"((R)[1]), "=r"((R)[2]), "=r"((R)[3])     \
                 : "r"(ADDR))

#define MMA16816(C, A, B0, B1)                                                \
    asm volatile("mma.sync.aligned.m16n8k16.row.col.f32.bf16.bf16.f32 "       \
                 "{%0,%1,%2,%3}, {%4,%5,%6,%7}, {%8,%9}, {%0,%1,%2,%3};"      \
                 : "+f"((C)[0]), "+f"((C)[1]), "+f"((C)[2]), "+f"((C)[3])     \
                 : "r"((A)[0]), "r"((A)[1]), "r"((A)[2]), "r"((A)[3]),        \
                   "r"(B0), "r"(B1))

#define CP_ASYNC16(DST, SRC)                                                  \
    asm volatile("cp.async.cg.shared.global [%0], [%1], 16;"                  \
                 :: "r"(DST), "l"(SRC) : "memory")

// ---------------------------------------------------------------------------
// Masked GEMM via mma.sync bf16 3-way split (hi*hi + hi*lo + lo*hi, f32 acc).
// Staging: DOUBLE-BUFFERED cp.async pipeline (wait_group 1) — only stage 0's
// DRAM latency is exposed; stages 1..3 overlap with convert of the previous.
// ---------------------------------------------------------------------------
__global__ void __launch_bounds__(128)
mma_gemm_kernel(const float* __restrict__ feat,
                const float* __restrict__ Wm,     // [64][64] (k, c)
                const float* __restrict__ bm,     // [64]
                float* __restrict__ out) {
    __shared__ __align__(1024) unsigned char sAhi[TPX * 128];  // 16 KB
    __shared__ __align__(1024) unsigned char sAlo[TPX * 128];  // 16 KB
    __shared__ __align__(1024) unsigned char sBhi[64 * 128];   // 8 KB
    __shared__ __align__(1024) unsigned char sBlo[64 * 128];   // 8 KB
    __shared__ __align__(1024) float sF[2][16 * 128];          // 16 KB (64 KB)

    const int tid  = threadIdx.x;
    const int warp = tid >> 5;
    const int lane = tid & 31;
    const int b    = blockIdx.y;
    const int hw0  = blockIdx.x * TPX;

    const float* gsrc0 = feat + (size_t)b * CC * HWSZ + hw0;
    const uint32_t aHi = smem_u32(sAhi);
    const uint32_t aLo = smem_u32(sAlo);

    // Row/col for this thread's cp.async slice (4 x 16B per stage, coalesced)
    // idx = tid + j*128; row = idx>>5 (0..15), col = (idx&31)*16 bytes
    // --- Prologue: issue A stage 0 immediately (hidden behind B staging) ---
    {
        const uint32_t dst = smem_u32(sF[0]);
        #pragma unroll
        for (int j = 0; j < 4; j++) {
            int idx = tid + j * 128;
            int row = idx >> 5;
            int col = (idx & 31) << 4;
            CP_ASYNC16(dst + row * 512 + col,
                       (const char*)(gsrc0 + (size_t)row * HWSZ) + col);
        }
        asm volatile("cp.async.commit_group;" ::: "memory");
    }

    // --- Stage B = W^T split (overlaps with A stage-0 cp.async) ---
    for (int i = tid; i < 64 * 64; i += 128) {
        int n = i & 63;
        int k = i >> 6;
        float w = Wm[k * 64 + n];
        __nv_bfloat16 h = __float2bfloat16(w);
        __nv_bfloat16 l = __float2bfloat16(w - __bfloat162float(h));
        uint32_t off = SWZ((uint32_t)(n * 128 + k * 2));
        *reinterpret_cast<unsigned short*>(sBhi + off) = __bfloat16_as_ushort(h);
        *reinterpret_cast<unsigned short*>(sBlo + off) = __bfloat16_as_ushort(l);
    }

    // --- A pipeline: 4 stages, depth-2 ---
    #pragma unroll
    for (int s = 0; s < 4; s++) {
        if (s + 1 < 4) {
            const uint32_t dst = smem_u32(sF[(s + 1) & 1]);
            const float* gs = gsrc0 + (size_t)((s + 1) * 16) * HWSZ;
            #pragma unroll
            for (int j = 0; j < 4; j++) {
                int idx = tid + j * 128;
                int row = idx >> 5;
                int col = (idx & 31) << 4;
                CP_ASYNC16(dst + row * 512 + col,
                           (const char*)(gs + (size_t)row * HWSZ) + col);
            }
            asm volatile("cp.async.commit_group;" ::: "memory");
            asm volatile("cp.async.wait_group 1;" ::: "memory");
        } else {
            asm volatile("cp.async.wait_group 0;" ::: "memory");
        }
        __syncthreads();

        // Convert stage s: thread = pixel; 16 conflict-free LDS, 4 STS.128
        const float* fs = sF[s & 1];
        float v[16];
        #pragma unroll
        for (int j = 0; j < 16; j++) v[j] = fs[j * 128 + tid];
        uint32_t hp[8], lp[8];
        #pragma unroll
        for (int j = 0; j < 8; j++) {
            __nv_bfloat16 h0 = __float2bfloat16(v[2 * j]);
            __nv_bfloat16 h1 = __float2bfloat16(v[2 * j + 1]);
            __nv_bfloat16 l0 = __float2bfloat16(v[2 * j] - __bfloat162float(h0));
            __nv_bfloat16 l1 = __float2bfloat16(v[2 * j + 1] - __bfloat162float(h1));
            hp[j] = (uint32_t)__bfloat16_as_ushort(h0) |
                    ((uint32_t)__bfloat16_as_ushort(h1) << 16);
            lp[j] = (uint32_t)__bfloat16_as_ushort(l0) |
                    ((uint32_t)__bfloat16_as_ushort(l1) << 16);
        }
        const uint32_t base = (uint32_t)tid * 128 + (uint32_t)s * 32;
        const uint32_t o0 = SWZ(base), o1 = SWZ(base + 16);
        asm volatile("st.shared.v4.b32 [%0], {%1, %2, %3, %4};"
                     :: "r"(aHi + o0), "r"(hp[0]), "r"(hp[1]), "r"(hp[2]), "r"(hp[3]) : "memory");
        asm volatile("st.shared.v4.b32 [%0], {%1, %2, %3, %4};"
                     :: "r"(aHi + o1), "r"(hp[4]), "r"(hp[5]), "r"(hp[6]), "r"(hp[7]) : "memory");
        asm volatile("st.shared.v4.b32 [%0], {%1, %2, %3, %4};"
                     :: "r"(aLo + o0), "r"(lp[0]), "r"(lp[1]), "r"(lp[2]), "r"(lp[3]) : "memory");
        asm volatile("st.shared.v4.b32 [%0], {%1, %2, %3, %4};"
                     :: "r"(aLo + o1), "r"(lp[4]), "r"(lp[5]), "r"(lp[6]), "r"(lp[7]) : "memory");
        __syncthreads();   // reads of sF[s&1] done before iter s+2 reissues it
    }

    // --- Fragment addressing (XOR applied to composed chunk offset) ---
    const int g = lane >> 2, t = lane & 3;
    const int px = warp * 32;
    const uint32_t mask   = (uint32_t)(lane & 7) << 4;
    const uint32_t aRow   = (uint32_t)(px + (lane & 15)) * 128;
    const uint32_t aChunk = (uint32_t)(lane & 16);
    const uint32_t bRow   = (uint32_t)((lane & 7) + ((lane & 16) >> 1)) * 128;
    const uint32_t bChunk = (uint32_t)((lane & 8) << 1);

    // Prefetch epilogue operands (overlap with MMA latency)
    const unsigned char* occp = g_occ + b * HWSZ + hw0 + px + g;
    unsigned char oc0 = occp[0], oc1 = occp[8], oc2 = occp[16], oc3 = occp[24];
    float bias0[8], bias1[8];
    #pragma unroll
    for (int n = 0; n < 8; n++) {
        bias0[n] = __ldg(&bm[n * 8 + 2 * t]);
        bias1[n] = __ldg(&bm[n * 8 + 2 * t + 1]);
    }

    float c_[2][8][4];
    #pragma unroll
    for (int m = 0; m < 2; m++)
        #pragma unroll
        for (int n = 0; n < 8; n++)
            #pragma unroll
            for (int r = 0; r < 4; r++) c_[m][n][r] = 0.0f;

    const uint32_t aBases[3] = { aHi, aHi, aLo };
    const uint32_t bBases[3] = { smem_u32(sBhi), smem_u32(sBlo), smem_u32(sBhi) };

    #pragma unroll
    for (int ps = 0; ps < 3; ps++) {
        const uint32_t aB = aBases[ps] + aRow;
        const uint32_t bB = bBases[ps] + bRow;
        #pragma unroll
        for (int k = 0; k < 4; k++) {
            const uint32_t ac = (aChunk + (uint32_t)k * 32) ^ mask;  // <=112, no carry
            const uint32_t bc = (bChunk + (uint32_t)k * 32) ^ mask;
            uint32_t a0[4], a1[4];
            LDSM4(a0, aB + ac);
            LDSM4(a1, aB + 2048 + ac);
            uint32_t bf[8][2];
            #pragma unroll
            for (int np = 0; np < 4; np++) {
                uint32_t r4[4];
                LDSM4(r4, bB + (uint32_t)np * 2048 + bc);
                bf[2 * np][0] = r4[0]; bf[2 * np][1] = r4[1];
                bf[2 * np + 1][0] = r4[2]; bf[2 * np + 1][1] = r4[3];
            }
            #pragma unroll
            for (int n = 0; n < 8; n++) {
                MMA16816(c_[0][n], a0, bf[n][0], bf[n][1]);
                MMA16816(c_[1][n], a1, bf[n][0], bf[n][1]);
            }
        }
    }

    // --- Epilogue: mask + bias; per-channel stores are full 32B sectors ---
    float msk[4];
    msk[0] = oc0 ? 1.0f : 0.0f;
    msk[1] = oc1 ? 1.0f : 0.0f;
    msk[2] = oc2 ? 1.0f : 0.0f;
    msk[3] = oc3 ? 1.0f : 0.0f;

    float* ob = out + (size_t)b * CC * HWSZ;
    #pragma unroll
    for (int m = 0; m < 2; m++) {
        const int hwA = hw0 + px + m * 16 + g;
        const int hwB = hwA + 8;
        const float mA = msk[2 * m], mB = msk[2 * m + 1];
        #pragma unroll
        for (int n = 0; n < 8; n++) {
            const size_t ch = (size_t)(n * 8 + 2 * t);
            ob[ch * HWSZ + hwA]       = (c_[m][n][0] + bias0[n]) * mA;
            ob[(ch + 1) * HWSZ + hwA] = (c_[m][n][1] + bias1[n]) * mA;
            ob[ch * HWSZ + hwB]       = (c_[m][n][2] + bias0[n]) * mB;
            ob[(ch + 1) * HWSZ + hwB] = (c_[m][n][3] + bias1[n]) * mB;
        }
    }
}

// ---------------------------------------------------------------------------
extern "C" void kernel_launch(void* const* d_in, const int* in_sizes, int n_in,
                              void* d_out, int out_size) {
    const float* feat = (const float*)d_in[0];      // [B, C, H, W] f32
    const void*  pidx = d_in[1];                    // [B, P, L] int32 or int64
    const float* Wm   = (const float*)d_in[2];      // [C, C] f32
    const float* bm   = (const float*)d_in[3];      // [C] f32
    float*       out  = (float*)d_out;              // [B, C, H, W] f32

    (void)in_sizes; (void)n_in; (void)out_size;

    zero_probe_kernel<<<(BB * HWSZ / 16 + 255) / 256, 256>>>((const int*)pidx);
    mark_occ_kernel<<<(NSTEPS + 255) / 256, 256>>>(pidx);

    dim3 grid(HWSZ / TPX, BB);   // 288 x 16 = 4608 tiles
    mma_gemm_kernel<<<grid, 128>>>(feat, Wm, bm, out);
}

// round 10
// speedup vs baseline: 1.2492x; 1.2211x over previous
#include <cuda_runtime.h>
#include <cuda_bf16.h>
#include <cstdint>

#define BB 16
#define CC 64
#define HH 192
#define WWID 192
#define HWSZ (HH * WWID)          // 36864
#define NSTEPS (BB * 128 * 512)   // 1,048,576 path steps
#define TPX 128                   // pixels per tile (MMA M)
#define NTILES (BB * (HWSZ / TPX))  // 4608
#define NCTAS (148 * 3)           // persistent grid

__device__ unsigned char g_occ[BB * HWSZ];
__device__ int g_idx_is64;

// ---------------------------------------------------------------------------
// Zero occupancy flags + probe path_idx element width (int64 hi-words == 0).
// ---------------------------------------------------------------------------
__global__ void zero_probe_kernel(const int* __restrict__ words) {
    int i = blockIdx.x * blockDim.x + threadIdx.x;
    uint4* p = reinterpret_cast<uint4*>(g_occ);
    if (i < (BB * HWSZ) / 16) p[i] = make_uint4(0u, 0u, 0u, 0u);
    if (i == 0) g_idx_is64 = 1;
    if (i < 1024 && words[2 * i + 1] != 0) atomicAnd(&g_idx_is64, 0);
}

__global__ void mark_occ_kernel(const void* __restrict__ path_idx) {
    int i = blockIdx.x * blockDim.x + threadIdx.x;
    if (i < NSTEPS) {
        int b = i >> 16;
        int hw;
        if (g_idx_is64)
            hw = (int)((const long long*)path_idx)[i];
        else
            hw = ((const int*)path_idx)[i];
        if ((unsigned)hw < (unsigned)HWSZ)
            g_occ[b * HWSZ + hw] = 1;
    }
}

// ---------------------------------------------------------------------------
__device__ __forceinline__ uint32_t smem_u32(const void* p) {
    uint32_t a;
    asm("{ .reg .u64 t; cvta.to.shared.u64 t, %1; cvt.u32.u64 %0, t; }"
        : "=r"(a) : "l"(p));
    return a;
}
#define SWZ(o) ((uint32_t)(o) ^ ((((uint32_t)(o)) >> 3) & 0x70))

#define LDSM4(R, ADDR)                                                        \
    asm volatile("ldmatrix.sync.aligned.m8n8.x4.shared.b16 {%0,%1,%2,%3}, [%4];" \
                 : "=r"((R)[0]), "=r"((R)[1]), "=r"((R)[2]), "=r"((R)[3])     \
                 : "r"(ADDR))

#define MMA16816(C, A, B0, B1)                                                \
    asm volatile("mma.sync.aligned.m16n8k16.row.col.f32.bf16.bf16.f32 "       \
                 "{%0,%1,%2,%3}, {%4,%5,%6,%7}, {%8,%9}, {%0,%1,%2,%3};"      \
                 : "+f"((C)[0]), "+f"((C)[1]), "+f"((C)[2]), "+f"((C)[3])     \
                 : "r"((A)[0]), "r"((A)[1]), "r"((A)[2]), "r"((A)[3]),        \
                   "r"(B0), "r"(B1))

// ---------------------------------------------------------------------------
// Persistent masked GEMM: each CTA loops over tiles. Per tile, the R6 core:
// register-batched LDG staging of A (f32 -> bf16 hi/lo split, transposed),
// one sync, 3-pass mma.sync (hi*hi + hi*lo + lo*hi), masked epilogue.
// B = W^T split staged ONCE per CTA.
// ---------------------------------------------------------------------------
__global__ void __launch_bounds__(128, 3)
mma_gemm_kernel(const float* __restrict__ feat,
                const float* __restrict__ Wm,     // [64][64] (k, c)
                const float* __restrict__ bm,     // [64]
                float* __restrict__ out) {
    __shared__ __align__(1024) unsigned char sAhi[TPX * 128];  // 16 KB
    __shared__ __align__(1024) unsigned char sAlo[TPX * 128];  // 16 KB
    __shared__ __align__(1024) unsigned char sBhi[64 * 128];   // 8 KB
    __shared__ __align__(1024) unsigned char sBlo[64 * 128];   // 8 KB (48 KB)

    const int tid  = threadIdx.x;
    const int warp = tid >> 5;
    const int lane = tid & 31;

    // --- Stage B = W^T split ONCE. Bt[n][k] = Wm[k][n]; 128 B rows ---
    for (int i = tid; i < 64 * 64; i += 128) {
        int n = i & 63;
        int k = i >> 6;
        float w = Wm[k * 64 + n];
        __nv_bfloat16 h = __float2bfloat16(w);
        __nv_bfloat16 l = __float2bfloat16(w - __bfloat162float(h));
        uint32_t off = SWZ((uint32_t)(n * 128 + k * 2));
        *reinterpret_cast<unsigned short*>(sBhi + off) = __bfloat16_as_ushort(h);
        *reinterpret_cast<unsigned short*>(sBlo + off) = __bfloat16_as_ushort(l);
    }

    // --- Loop-invariant fragment addressing ---
    const int g = lane >> 2, t = lane & 3;
    const int px = warp * 32;
    const uint32_t mask   = (uint32_t)(lane & 7) << 4;
    const uint32_t aRow   = (uint32_t)(px + (lane & 15)) * 128;
    const uint32_t aChunk = (uint32_t)(lane & 16);
    const uint32_t bRow   = (uint32_t)((lane & 7) + ((lane & 16) >> 1)) * 128;
    const uint32_t bChunk = (uint32_t)((lane & 8) << 1);
    const uint32_t aHi = smem_u32(sAhi);
    const uint32_t aLo = smem_u32(sAlo);
    const uint32_t aBases[3] = { aHi, aHi, aLo };
    const uint32_t bBases[3] = { smem_u32(sBhi), smem_u32(sBlo), smem_u32(sBhi) };

    // --- Persistent tile loop ---
    for (int tile = blockIdx.x; tile < NTILES; tile += NCTAS) {
        const int b   = tile / (HWSZ / TPX);
        const int hw0 = (tile - b * (HWSZ / TPX)) * TPX;

        // Stage A: thread = pixel; 64 batched strided LDGs, convert, STS.128
        {
            const float* fbase = feat + (size_t)b * CC * HWSZ + hw0 + tid;
            const uint32_t arow = (uint32_t)tid * 128;
            #pragma unroll
            for (int c = 0; c < 8; c++) {
                uint32_t hp[4], lp[4];
                #pragma unroll
                for (int j = 0; j < 4; j++) {
                    int k0 = c * 8 + 2 * j;
                    float a0 = fbase[(size_t)k0 * HWSZ];
                    float a1 = fbase[(size_t)(k0 + 1) * HWSZ];
                    __nv_bfloat16 h0 = __float2bfloat16(a0);
                    __nv_bfloat16 h1 = __float2bfloat16(a1);
                    __nv_bfloat16 l0 = __float2bfloat16(a0 - __bfloat162float(h0));
                    __nv_bfloat16 l1 = __float2bfloat16(a1 - __bfloat162float(h1));
                    hp[j] = (uint32_t)__bfloat16_as_ushort(h0) |
                            ((uint32_t)__bfloat16_as_ushort(h1) << 16);
                    lp[j] = (uint32_t)__bfloat16_as_ushort(l0) |
                            ((uint32_t)__bfloat16_as_ushort(l1) << 16);
                }
                uint32_t off = SWZ(arow + c * 16);
                asm volatile("st.shared.v4.b32 [%0], {%1, %2, %3, %4};"
                             :: "r"(aHi + off),
                                "r"(hp[0]), "r"(hp[1]), "r"(hp[2]), "r"(hp[3]) : "memory");
                asm volatile("st.shared.v4.b32 [%0], {%1, %2, %3, %4};"
                             :: "r"(aLo + off),
                                "r"(lp[0]), "r"(lp[1]), "r"(lp[2]), "r"(lp[3]) : "memory");
            }
        }
        __syncthreads();

        // MMA: 3 split passes x 4 K-steps
        float c_[2][8][4];
        #pragma unroll
        for (int m = 0; m < 2; m++)
            #pragma unroll
            for (int n = 0; n < 8; n++)
                #pragma unroll
                for (int r = 0; r < 4; r++) c_[m][n][r] = 0.0f;

        #pragma unroll
        for (int ps = 0; ps < 3; ps++) {
            const uint32_t aB = aBases[ps] + aRow;
            const uint32_t bB = bBases[ps] + bRow;
            #pragma unroll
            for (int k = 0; k < 4; k++) {
                const uint32_t ac = (aChunk + (uint32_t)k * 32) ^ mask;  // no carry
                const uint32_t bc = (bChunk + (uint32_t)k * 32) ^ mask;
                uint32_t a0[4], a1[4];
                LDSM4(a0, aB + ac);
                LDSM4(a1, aB + 2048 + ac);
                uint32_t bf[8][2];
                #pragma unroll
                for (int np = 0; np < 4; np++) {
                    uint32_t r4[4];
                    LDSM4(r4, bB + (uint32_t)np * 2048 + bc);
                    bf[2 * np][0] = r4[0]; bf[2 * np][1] = r4[1];
                    bf[2 * np + 1][0] = r4[2]; bf[2 * np + 1][1] = r4[3];
                }
                #pragma unroll
                for (int n = 0; n < 8; n++) {
                    MMA16816(c_[0][n], a0, bf[n][0], bf[n][1]);
                    MMA16816(c_[1][n], a1, bf[n][0], bf[n][1]);
                }
            }
        }

        // Epilogue: mask + bias; per-channel stores are full 32B sectors
        const unsigned char* occp = g_occ + b * HWSZ + hw0 + px + g;
        float msk[4];
        msk[0] = occp[0]  ? 1.0f : 0.0f;
        msk[1] = occp[8]  ? 1.0f : 0.0f;
        msk[2] = occp[16] ? 1.0f : 0.0f;
        msk[3] = occp[24] ? 1.0f : 0.0f;

        float bias0[8], bias1[8];
        #pragma unroll
        for (int n = 0; n < 8; n++) {
            bias0[n] = __ldg(&bm[n * 8 + 2 * t]);
            bias1[n] = __ldg(&bm[n * 8 + 2 * t + 1]);
        }

        float* ob = out + (size_t)b * CC * HWSZ;
        #pragma unroll
        for (int m = 0; m < 2; m++) {
            const int hwA = hw0 + px + m * 16 + g;
            const int hwB = hwA + 8;
            const float mA = msk[2 * m], mB = msk[2 * m + 1];
            #pragma unroll
            for (int n = 0; n < 8; n++) {
                const size_t ch = (size_t)(n * 8 + 2 * t);
                ob[ch * HWSZ + hwA]       = (c_[m][n][0] + bias0[n]) * mA;
                ob[(ch + 1) * HWSZ + hwA] = (c_[m][n][1] + bias1[n]) * mA;
                ob[ch * HWSZ + hwB]       = (c_[m][n][2] + bias0[n]) * mB;
                ob[(ch + 1) * HWSZ + hwB] = (c_[m][n][3] + bias1[n]) * mB;
            }
        }
        __syncthreads();   // all warps done reading sA before next staging
    }
}

// ---------------------------------------------------------------------------
extern "C" void kernel_launch(void* const* d_in, const int* in_sizes, int n_in,
                              void* d_out, int out_size) {
    const float* feat = (const float*)d_in[0];      // [B, C, H, W] f32
    const void*  pidx = d_in[1];                    // [B, P, L] int32 or int64
    const float* Wm   = (const float*)d_in[2];      // [C, C] f32
    const float* bm   = (const float*)d_in[3];      // [C] f32
    float*       out  = (float*)d_out;              // [B, C, H, W] f32

    (void)in_sizes; (void)n_in; (void)out_size;

    zero_probe_kernel<<<(BB * HWSZ / 16 + 255) / 256, 256>>>((const int*)pidx);
    mark_occ_kernel<<<(NSTEPS + 255) / 256, 256>>>(pidx);

    mma_gemm_kernel<<<NCTAS, 128>>>(feat, Wm, bm, out);
}